// round 7
// baseline (speedup 1.0000x reference)
#include <cuda_runtime.h>
#include <cuda_bf16.h>
#include <math.h>
#include <stdint.h>

// Problem constants
#define Bn   1024
#define Tn   512
#define Dn   64
#define Hn   256
#define G4   1024
#define MIDn 64
#define An   3

// ---- step kernel tiling: CTA = 128 rows x 64 gate-cols, K=256 (h only), 8 chunks of 32
#define APITCH 80                       // A smem row pitch (64B data + 16) -> conflict-free
#define BPITCH 528                      // B smem row pitch (512B data + 16)
#define ABUF   (3*128*APITCH)           // 30720 B per A buffer (3 planes)
#define NBUF   3
#define B_OFF  (NBUF*ABUF)              // 92160
#define GX_OFF (B_OFF + 3*64*BPITCH)    // 92160 + 101376 = 193536
#define GXPITCH 144                     // per-thread 128B data + 16 pad
#define SMEM_STEP (GX_OFF + 256*GXPITCH)  // 193536 + 36864 = 230400

// ---- gx kernel tiling: CTA = 128 rows x 64 cols, K=64
#define XPITCH 144
#define GA_OFF 0
#define GB_OFF (3*128*XPITCH)           // 55296
#define SMEM_GX (GB_OFF + 3*64*XPITCH)  // 55296 + 27648 = 82944

// ---------------- device scratch (static, no allocation) ----------------
__device__ __nv_bfloat16 g_W[3][G4][256];          // h-part weights [plane][gatecol][k]
__device__ __nv_bfloat16 g_Wx[3][G4][Dn];          // x-part weights [plane][gatecol][d]
__device__ __nv_bfloat16 g_x[3][Bn][Tn][Dn];       // split x
__device__ __nv_bfloat16 g_h[2][3][Bn][Hn];        // ping-pong split h
__device__ float g_br[G4];
__device__ float g_gx[(size_t)Tn*16*8*8192];       // fragment-linear x-gates (+bias), 2.1 GB
__device__ float g_hfull[Bn*Hn];
__device__ float g_a1[Bn*MIDn];
__device__ float g_v1[Bn*MIDn];
__device__ int   g_bar[8];

// ---------------- helpers ----------------
__device__ __forceinline__ void split3(float v, __nv_bfloat16& b1,
                                       __nv_bfloat16& b2, __nv_bfloat16& b3) {
    b1 = __float2bfloat16(v);
    float r = v - __bfloat162float(b1);
    b2 = __float2bfloat16(r);
    float r2 = r - __bfloat162float(b2);
    b3 = __float2bfloat16(r2);
}

__device__ __forceinline__ uint32_t smem_u32(const void* p) {
    uint32_t a;
    asm("{ .reg .u64 t; cvta.to.shared.u64 t, %1; cvt.u32.u64 %0, t; }" : "=r"(a) : "l"(p));
    return a;
}

__device__ __forceinline__ void cp16(uint32_t dst, const void* src) {
    asm volatile("cp.async.cg.shared.global [%0], [%1], 16;" :: "r"(dst), "l"(src) : "memory");
}
__device__ __forceinline__ void cp_commit() {
    asm volatile("cp.async.commit_group;" ::: "memory");
}

#define LDSM4(R, addr) \
    asm volatile("ldmatrix.sync.aligned.m8n8.x4.shared.b16 {%0,%1,%2,%3}, [%4];" \
        : "=r"((R)[0]), "=r"((R)[1]), "=r"((R)[2]), "=r"((R)[3]) : "r"(addr))

__device__ __forceinline__ void mma_bf16(float c[4], const uint32_t a[4],
                                         uint32_t b0, uint32_t b1) {
    asm volatile(
        "mma.sync.aligned.m16n8k16.row.col.f32.bf16.bf16.f32 "
        "{%0,%1,%2,%3}, {%4,%5,%6,%7}, {%8,%9}, {%0,%1,%2,%3};"
        : "+f"(c[0]), "+f"(c[1]), "+f"(c[2]), "+f"(c[3])
        : "r"(a[0]), "r"(a[1]), "r"(a[2]), "r"(a[3]), "r"(b0), "r"(b1));
}

// ---------------- prep kernels ----------------
// k-space: k 0..255 = h units (Wc rows 64+k); x dims d = Wc rows 0..63
__global__ void wsplit_kernel(const float* __restrict__ Wc, const float* __restrict__ bc) {
    int idx = blockIdx.x * blockDim.x + threadIdx.x;
    if (idx < G4 * 320) {
        int k = idx % 320;
        int gcol = idx / 320;
        int u = gcol >> 2, g = gcol & 3;
        __nv_bfloat16 s[3];
        if (k < 256) {
            float w = Wc[(64 + k) * G4 + g * Hn + u];
            split3(w, s[0], s[1], s[2]);
#pragma unroll
            for (int p = 0; p < 3; p++) g_W[p][gcol][k] = s[p];
        } else {
            int d = k - 256;
            float w = Wc[d * G4 + g * Hn + u];
            split3(w, s[0], s[1], s[2]);
#pragma unroll
            for (int p = 0; p < 3; p++) g_Wx[p][gcol][d] = s[p];
        }
    }
    if (idx < G4) {
        int u = idx >> 2, g = idx & 3;
        g_br[idx] = bc[g * Hn + u];
    }
}

__global__ void xsplit_kernel(const float* __restrict__ x) {
    int idx = blockIdx.x * blockDim.x + threadIdx.x;
    int d = idx & 63;
    int tt = (idx >> 6) & 511;
    int b = idx >> 15;
    if (b >= Bn) return;
    float v = x[((size_t)b * Tn + tt) * Dn + d];
    __nv_bfloat16 s[3];
    split3(v, s[0], s[1], s[2]);
#pragma unroll
    for (int p = 0; p < 3; p++) g_x[p][b][tt][d] = s[p];
}

__global__ void init_kernel() {
    int idx = blockIdx.x * blockDim.x + threadIdx.x;
    if (idx < 3 * Bn * Hn / 2)
        ((unsigned*)g_h[0])[idx] = 0u;
    if (idx < 8) g_bar[idx] = 0;
}

// ---------------- gx precompute: gates_x = x @ Wx + b (bf16x6), fragment-linear out ----
// grid (8, 16, 512): bi, ci, t. block 256.
__global__ __launch_bounds__(256, 2)
void gx_kernel() {
    extern __shared__ char dsm[];
    const uint32_t sbase = smem_u32(dsm);

    const int tid  = threadIdx.x;
    const int lane = tid & 31;
    const int warp = tid >> 5;
    const int wm = warp & 3;
    const int wn = warp >> 2;
    const int bi = blockIdx.x;
    const int ci = blockIdx.y;
    const int t  = blockIdx.z;
    const int row0 = bi * 128;

    // A: 3 planes x 128 rows x 128B   (12 cp16/thread)
#pragma unroll
    for (int i = 0; i < 12; i++) {
        int flat = i * 256 + tid;
        int q = flat & 7;
        int m = (flat >> 3) & 127;
        int p = flat >> 10;
        cp16(sbase + GA_OFF + (uint32_t)(p * 128 + m) * XPITCH + q * 16,
             (const char*)&g_x[p][row0 + m][t][q * 8]);
    }
    // B: 3 planes x 64 cols x 128B   (6 cp16/thread)
#pragma unroll
    for (int i = 0; i < 6; i++) {
        int flat = i * 256 + tid;
        int q = flat & 7;
        int n = (flat >> 3) & 63;
        int p = flat >> 9;
        cp16(sbase + GB_OFF + (uint32_t)(p * 64 + n) * XPITCH + q * 16,
             (const char*)&g_Wx[p][ci * 64 + n][q * 8]);
    }
    cp_commit();
    asm volatile("cp.async.wait_group 0;" ::: "memory");
    __syncthreads();

    const int mrow = lane & 15;
    const int kAo  = (lane >> 4) << 3;
    const int nBo  = ((lane >> 4) << 3) + (lane & 7);
    const int kBo  = ((lane >> 3) & 1) << 3;

    float cm[2][4][4], cl[2][4][4];
#pragma unroll
    for (int mi = 0; mi < 2; mi++)
#pragma unroll
        for (int ni = 0; ni < 4; ni++)
#pragma unroll
            for (int q = 0; q < 4; q++) { cm[mi][ni][q] = 0.0f; cl[mi][ni][q] = 0.0f; }

#pragma unroll
    for (int ks = 0; ks < 4; ks++) {
        uint32_t a[3][2][4], b[3][2][4];
#pragma unroll
        for (int p = 0; p < 3; p++) {
#pragma unroll
            for (int mi = 0; mi < 2; mi++)
                LDSM4(a[p][mi], sbase + GA_OFF
                      + (uint32_t)(p * 128 + wm * 32 + mi * 16 + mrow) * XPITCH
                      + (ks * 16 + kAo) * 2);
#pragma unroll
            for (int pr = 0; pr < 2; pr++)
                LDSM4(b[p][pr], sbase + GB_OFF
                      + (uint32_t)(p * 64 + wn * 32 + pr * 16 + nBo) * XPITCH
                      + (ks * 16 + kBo) * 2);
        }
#pragma unroll
        for (int mi = 0; mi < 2; mi++)
#pragma unroll
            for (int ni = 0; ni < 4; ni++) {
                const int pr = ni >> 1, o = (ni & 1) * 2;
                mma_bf16(cm[mi][ni], a[0][mi], b[0][pr][o], b[0][pr][o+1]);
                mma_bf16(cl[mi][ni], a[0][mi], b[1][pr][o], b[1][pr][o+1]);
                mma_bf16(cl[mi][ni], a[1][mi], b[0][pr][o], b[0][pr][o+1]);
                mma_bf16(cl[mi][ni], a[0][mi], b[2][pr][o], b[2][pr][o+1]);
                mma_bf16(cl[mi][ni], a[1][mi], b[1][pr][o], b[1][pr][o+1]);
                mma_bf16(cl[mi][ni], a[2][mi], b[0][pr][o], b[0][pr][o+1]);
            }
    }

    // out: fragment-linear, +bias
    float* outp = g_gx + (((size_t)t * 16 + ci) * 8 + bi) * 8192 + (size_t)tid * 32;
#pragma unroll
    for (int mi = 0; mi < 2; mi++)
#pragma unroll
        for (int ni = 0; ni < 4; ni++) {
            int col = ci * 64 + wn * 32 + ni * 8 + (lane & 3) * 2;
            float b0 = g_br[col], b1 = g_br[col + 1];
            float4 v;
            v.x = cm[mi][ni][0] + cl[mi][ni][0] + b0;
            v.y = cm[mi][ni][1] + cl[mi][ni][1] + b1;
            v.z = cm[mi][ni][2] + cl[mi][ni][2] + b0;
            v.w = cm[mi][ni][3] + cl[mi][ni][3] + b1;
            *(float4*)&outp[mi * 16 + ni * 4] = v;
        }
}

// ---------------- persistent step kernel (h recurrence only, K=256) ----------------
// grid (8, 16): bi = batch slice (128 rows), ci = 16 hidden units (64 gate cols)
__global__ __launch_bounds__(256)
void step_kernel() {
    extern __shared__ char dsm[];
    const uint32_t sbase = smem_u32(dsm);

    const int tid  = threadIdx.x;
    const int lane = tid & 31;
    const int warp = tid >> 5;
    const int wm = warp & 3;
    const int wn = warp >> 2;
    const int bi = blockIdx.x;
    const int ci = blockIdx.y;
    const int row0 = bi * 128;

    // resident B (h weights): 3 planes x 64 cols x 512B  (24 cp16/thread)
#pragma unroll
    for (int i = 0; i < 24; i++) {
        int flat = i * 256 + tid;
        int q = flat & 31;
        int n = (flat >> 5) & 63;
        int p = flat >> 11;
        cp16(sbase + B_OFF + (uint32_t)(p * 64 + n) * BPITCH + q * 16,
             (const char*)&g_W[p][ci * 64 + n][q * 8]);
    }
    cp_commit();   // group retires FIFO before first consume

    float cold[8], nold[8];
#pragma unroll
    for (int q = 0; q < 8; q++) { cold[q] = 0.0f; nold[q] = 1.0f; }

    const int mrow = lane & 15;
    const int kAo  = (lane >> 4) << 3;
    const int nBo  = ((lane >> 4) << 3) + (lane & 7);
    const int kBo  = ((lane >> 3) & 1) << 3;
    const bool odd = lane & 1;
    const int jh = (lane >> 1) & 1;

    const size_t gxstride = (size_t)16 * 8 * 8192;
    const size_t gxbase0 = ((size_t)ci * 8 + bi) * 8192 + (size_t)tid * 32;

    for (int t = 0; t < Tn; t++) {
        const int hbuf = t & 1;

        // gx prefetch (no h dependence) - before barrier
        {
            const float* src = g_gx + (size_t)t * gxstride + gxbase0;
#pragma unroll
            for (int j = 0; j < 8; j++)
                cp16(sbase + GX_OFF + (uint32_t)tid * GXPITCH + j * 16, src + j * 4);
            cp_commit();
        }

        // wait for h(t) from all 16 CTAs of this bi group
        if (t > 0) {
            if (tid == 0) {
                const int target = 16 * t;
                while (((volatile int*)g_bar)[bi] < target) { }
                __threadfence();
            }
            __syncthreads();
        }

        auto issue_chunk = [&](int ch, int buf) {
#pragma unroll
            for (int i = 0; i < 6; i++) {
                int flat = i * 256 + tid;
                int q = flat & 3;
                int m = (flat >> 2) & 127;
                int p = flat >> 9;
                cp16(sbase + (uint32_t)(buf * 3 + p) * (128 * APITCH)
                     + (uint32_t)m * APITCH + q * 16,
                     (const char*)&g_h[hbuf][p][row0 + m][ch * 32 + q * 8]);
            }
            cp_commit();
        };

        issue_chunk(0, 0);
        issue_chunk(1, 1);
        issue_chunk(2, 2);

        float cm[2][4][4], cl[2][4][4];
#pragma unroll
        for (int mi = 0; mi < 2; mi++)
#pragma unroll
            for (int ni = 0; ni < 4; ni++)
#pragma unroll
                for (int q = 0; q < 4; q++) { cm[mi][ni][q] = 0.0f; cl[mi][ni][q] = 0.0f; }

#pragma unroll 1
        for (int ch = 0; ch < 8; ch++) {
            if (ch < 6)       asm volatile("cp.async.wait_group 2;" ::: "memory");
            else if (ch == 6) asm volatile("cp.async.wait_group 1;" ::: "memory");
            else              asm volatile("cp.async.wait_group 0;" ::: "memory");
            __syncthreads();

            const int buf = ch % NBUF;
            const uint32_t abase = sbase + (uint32_t)buf * ABUF;
            const uint32_t bko = (uint32_t)(ch * 32) * 2;

            uint32_t a0[3][2][4], b0[3][2][4], a1[3][2][4], b1[3][2][4];
#pragma unroll
            for (int p = 0; p < 3; p++) {
#pragma unroll
                for (int mi = 0; mi < 2; mi++) {
                    uint32_t ad = abase + (uint32_t)(p * 128 + wm * 32 + mi * 16 + mrow) * APITCH;
                    LDSM4(a0[p][mi], ad + (0 + kAo) * 2);
                    LDSM4(a1[p][mi], ad + (16 + kAo) * 2);
                }
#pragma unroll
                for (int pr = 0; pr < 2; pr++) {
                    uint32_t bd = sbase + B_OFF
                                + (uint32_t)(p * 64 + wn * 32 + pr * 16 + nBo) * BPITCH + bko;
                    LDSM4(b0[p][pr], bd + (0 + kBo) * 2);
                    LDSM4(b1[p][pr], bd + (16 + kBo) * 2);
                }
            }
            __syncthreads();
            if (ch + 3 < 8) issue_chunk(ch + 3, buf);

#pragma unroll
            for (int mi = 0; mi < 2; mi++)
#pragma unroll
                for (int ni = 0; ni < 4; ni++) {
                    const int pr = ni >> 1, o = (ni & 1) * 2;
                    mma_bf16(cm[mi][ni], a0[0][mi], b0[0][pr][o], b0[0][pr][o+1]);
                    mma_bf16(cl[mi][ni], a0[0][mi], b0[1][pr][o], b0[1][pr][o+1]);
                    mma_bf16(cl[mi][ni], a0[1][mi], b0[0][pr][o], b0[0][pr][o+1]);
                    mma_bf16(cl[mi][ni], a0[0][mi], b0[2][pr][o], b0[2][pr][o+1]);
                    mma_bf16(cl[mi][ni], a0[1][mi], b0[1][pr][o], b0[1][pr][o+1]);
                    mma_bf16(cl[mi][ni], a0[2][mi], b0[0][pr][o], b0[0][pr][o+1]);
                    mma_bf16(cm[mi][ni], a1[0][mi], b1[0][pr][o], b1[0][pr][o+1]);
                    mma_bf16(cl[mi][ni], a1[0][mi], b1[1][pr][o], b1[1][pr][o+1]);
                    mma_bf16(cl[mi][ni], a1[1][mi], b1[0][pr][o], b1[0][pr][o+1]);
                    mma_bf16(cl[mi][ni], a1[0][mi], b1[2][pr][o], b1[2][pr][o+1]);
                    mma_bf16(cl[mi][ni], a1[1][mi], b1[1][pr][o], b1[1][pr][o+1]);
                    mma_bf16(cl[mi][ni], a1[2][mi], b1[0][pr][o], b1[0][pr][o+1]);
                }
        }

        // ---- epilogue ----
        __syncthreads();                           // all LDSMs done; Hs aliases buf0
        __nv_bfloat16* Hs = (__nv_bfloat16*)dsm;   // [3][128][16]
        const bool last = (t == Tn - 1);

#pragma unroll
        for (int mi = 0; mi < 2; mi++)
#pragma unroll
            for (int ni = 0; ni < 4; ni++) {
                float4 gx = *(const float4*)(dsm + GX_OFF + tid * GXPITCH + (mi * 4 + ni) * 16);
                float q0 = (cm[mi][ni][0] + cl[mi][ni][0]) + gx.x;
                float q1 = (cm[mi][ni][1] + cl[mi][ni][1]) + gx.y;
                float q2 = (cm[mi][ni][2] + cl[mi][ni][2]) + gx.z;
                float q3 = (cm[mi][ni][3] + cl[mi][ni][3]) + gx.w;
                float s0 = __shfl_xor_sync(0xFFFFFFFFu, q0, 1);
                float s1 = __shfl_xor_sync(0xFFFFFFFFu, q1, 1);
                float s2 = __shfl_xor_sync(0xFFFFFFFFu, q2, 1);
                float s3 = __shfl_xor_sync(0xFFFFFFFFu, q3, 1);

                float gi = odd ? s2 : q0;
                float gf = odd ? s3 : q1;
                float go = odd ? q2 : s0;
                float gz = odd ? q3 : s1;

                const int row = wm * 32 + mi * 16 + (lane >> 2) + (odd ? 8 : 0);
                const int ul  = wn * 8 + ni * 2 + jh;
                const int qi  = mi * 4 + ni;

                gi = fminf(fmaxf(gi, -5.0f), 5.0f);
                gf = fminf(fmaxf(gf, -5.0f), 5.0f);
                float iv = __expf(gi);
                float fv = __expf(gf);

                float cv = fv * cold[qi] + iv * (1.0f - 2.0f / (__expf(2.0f * gz) + 1.0f));
                cv = fminf(fmaxf(cv, -1e6f), 1e6f);
                float nv = fv * nold[qi] + iv;
                nv = fminf(fmaxf(nv, 1e-6f), 1e6f);
                cold[qi] = cv;
                nold[qi] = nv;

                float ov = 1.0f / (1.0f + __expf(-go));
                float hv = ov * (cv / nv);
                if (!isfinite(hv)) hv = 0.0f;

                __nv_bfloat16 h1, h2, h3;
                split3(hv, h1, h2, h3);
                Hs[(0 * 128 + row) * 16 + ul] = h1;
                Hs[(1 * 128 + row) * 16 + ul] = h2;
                Hs[(2 * 128 + row) * 16 + ul] = h3;
                if (last) g_hfull[(row0 + row) * Hn + ci * 16 + ul] = hv;
            }
        __syncthreads();

        if (!last) {
            const int nbuf = hbuf ^ 1;
#pragma unroll
            for (int i = 0; i < 3; i++) {
                int flat = i * 256 + tid;
                int q = flat & 1;
                int m = (flat >> 1) & 127;
                int p = flat >> 8;
                uint4 v = *(const uint4*)&Hs[(p * 128 + m) * 16 + q * 8];
                *(uint4*)&g_h[nbuf][p][row0 + m][ci * 16 + q * 8] = v;
            }
            __threadfence();
            __syncthreads();
            if (tid == 0) atomicAdd(&g_bar[bi], 1);
        }
    }
}

// ---------------- heads ----------------
__global__ void heads1_kernel(const float* __restrict__ Wa1, const float* __restrict__ ba1,
                              const float* __restrict__ Wv1, const float* __restrict__ bv1) {
    int idx = blockIdx.x * blockDim.x + threadIdx.x;
    if (idx >= Bn * 128) return;
    int b = idx >> 7;
    int j = idx & 127;
    const float* hrow = g_hfull + b * Hn;
    if (j < MIDn) {
        float s = ba1[j];
#pragma unroll 8
        for (int k = 0; k < Hn; k++) s = fmaf(hrow[k], Wa1[k * MIDn + j], s);
        g_a1[b * MIDn + j] = fmaxf(s, 0.0f);
    } else {
        int jj = j - MIDn;
        float s = bv1[jj];
#pragma unroll 8
        for (int k = 0; k < Hn; k++) s = fmaf(hrow[k], Wv1[k * MIDn + jj], s);
        g_v1[b * MIDn + jj] = fmaxf(s, 0.0f);
    }
}

__global__ void heads2_kernel(const float* __restrict__ Wa2, const float* __restrict__ ba2,
                              const float* __restrict__ Wv2, const float* __restrict__ bv2,
                              float* __restrict__ out) {
    int b = blockIdx.x * blockDim.x + threadIdx.x;
    if (b >= Bn) return;
    float l0 = ba2[0], l1 = ba2[1], l2 = ba2[2];
#pragma unroll 8
    for (int m = 0; m < MIDn; m++) {
        float a = g_a1[b * MIDn + m];
        l0 = fmaf(a, Wa2[m * An + 0], l0);
        l1 = fmaf(a, Wa2[m * An + 1], l1);
        l2 = fmaf(a, Wa2[m * An + 2], l2);
    }
    float mx = fmaxf(l0, fmaxf(l1, l2));
    float e0 = expf(l0 - mx), e1 = expf(l1 - mx), e2 = expf(l2 - mx);
    float s = e0 + e1 + e2;
    out[b * An + 0] = e0 / s;
    out[b * An + 1] = e1 / s;
    out[b * An + 2] = e2 / s;

    float v = bv2[0];
#pragma unroll 8
    for (int m = 0; m < MIDn; m++) v = fmaf(g_v1[b * MIDn + m], Wv2[m], v);
    out[Bn * An + b] = v;
}

// ---------------- launch ----------------
extern "C" void kernel_launch(void* const* d_in, const int* in_sizes, int n_in,
                              void* d_out, int out_size) {
    const float* x   = (const float*)d_in[0];
    const float* Wc  = (const float*)d_in[1];
    const float* bc  = (const float*)d_in[2];
    const float* Wa1 = (const float*)d_in[3];
    const float* ba1 = (const float*)d_in[4];
    const float* Wa2 = (const float*)d_in[5];
    const float* ba2 = (const float*)d_in[6];
    const float* Wv1 = (const float*)d_in[7];
    const float* bv1 = (const float*)d_in[8];
    const float* Wv2 = (const float*)d_in[9];
    const float* bv2 = (const float*)d_in[10];
    float* out = (float*)d_out;

    cudaFuncSetAttribute(step_kernel, cudaFuncAttributeMaxDynamicSharedMemorySize, SMEM_STEP);
    cudaFuncSetAttribute(gx_kernel,   cudaFuncAttributeMaxDynamicSharedMemorySize, SMEM_GX);

    wsplit_kernel<<<(G4 * 320 + 255) / 256, 256>>>(Wc, bc);
    xsplit_kernel<<<(Bn * Tn * Dn + 255) / 256, 256>>>(x);
    init_kernel<<<(3 * Bn * Hn / 2 + 255) / 256, 256>>>();

    gx_kernel<<<dim3(8, 16, Tn), 256, SMEM_GX>>>();
    step_kernel<<<dim3(8, 16), 256, SMEM_STEP>>>();

    heads1_kernel<<<(Bn * 128 + 255) / 256, 256>>>(Wa1, ba1, Wv1, bv1);
    heads2_kernel<<<(Bn + 255) / 256, 256>>>(Wa2, ba2, Wv2, bv2, out);
}

// round 8
// speedup vs baseline: 1.3538x; 1.3538x over previous
#include <cuda_runtime.h>
#include <cuda_bf16.h>
#include <math.h>
#include <stdint.h>

// Problem constants
#define Bn   1024
#define Tn   512
#define Dn   64
#define Hn   256
#define G4   1024
#define MIDn 64
#define An   3

// CTA = 128 rows x 64 gate-cols. K=320: x chunk k[256..320) first, then 4 h chunks k=64.
// A buffers: XOR-swizzled, pitch 128B (no pad). B resident: pitch 640B, XOR-swizzled.
#define ABUF   (3*128*128)              // 49152 B per A buffer (3 planes)
#define NBUF   2
#define B_OFF  (NBUF*ABUF)              // 98304
#define BPITCH 640
#define SMEM_TOT (B_OFF + 3*64*BPITCH)  // 98304 + 122880 = 221184

// ---------------- device scratch (static, no allocation) ----------------
__device__ __nv_bfloat16 g_W[3][G4][320];          // [plane][gatecol][k] k0..255=h, 256..319=x
__device__ __nv_bfloat16 g_xT[3][Tn][Bn][Dn];      // split x, t-major
__device__ __nv_bfloat16 g_h[2][3][Bn][Hn];        // ping-pong split h
__device__ float g_br[G4];
__device__ float g_hfull[Bn*Hn];
__device__ float g_a1[Bn*MIDn];
__device__ float g_v1[Bn*MIDn];
__device__ int   g_bar[8];

// ---------------- helpers ----------------
__device__ __forceinline__ void split3(float v, __nv_bfloat16& b1,
                                       __nv_bfloat16& b2, __nv_bfloat16& b3) {
    b1 = __float2bfloat16(v);
    float r = v - __bfloat162float(b1);
    b2 = __float2bfloat16(r);
    float r2 = r - __bfloat162float(b2);
    b3 = __float2bfloat16(r2);
}

__device__ __forceinline__ uint32_t smem_u32(const void* p) {
    uint32_t a;
    asm("{ .reg .u64 t; cvta.to.shared.u64 t, %1; cvt.u32.u64 %0, t; }" : "=r"(a) : "l"(p));
    return a;
}

__device__ __forceinline__ void cp16(uint32_t dst, const void* src) {
    asm volatile("cp.async.cg.shared.global [%0], [%1], 16;" :: "r"(dst), "l"(src) : "memory");
}
__device__ __forceinline__ void cp_commit() {
    asm volatile("cp.async.commit_group;" ::: "memory");
}

#define LDSM4(R, addr) \
    asm volatile("ldmatrix.sync.aligned.m8n8.x4.shared.b16 {%0,%1,%2,%3}, [%4];" \
        : "=r"((R)[0]), "=r"((R)[1]), "=r"((R)[2]), "=r"((R)[3]) : "r"(addr))

__device__ __forceinline__ void mma_bf16(float c[4], const uint32_t a[4],
                                         uint32_t b0, uint32_t b1) {
    asm volatile(
        "mma.sync.aligned.m16n8k16.row.col.f32.bf16.bf16.f32 "
        "{%0,%1,%2,%3}, {%4,%5,%6,%7}, {%8,%9}, {%0,%1,%2,%3};"
        : "+f"(c[0]), "+f"(c[1]), "+f"(c[2]), "+f"(c[3])
        : "r"(a[0]), "r"(a[1]), "r"(a[2]), "r"(a[3]), "r"(b0), "r"(b1));
}

// ---------------- prep kernels ----------------
// k-space: k 0..255 = h units (Wc rows 64+k), k 256..319 = x dims (Wc rows k-256)
__global__ void wsplit_kernel(const float* __restrict__ Wc, const float* __restrict__ bc) {
    int idx = blockIdx.x * blockDim.x + threadIdx.x;
    if (idx < G4 * 320) {
        int k = idx % 320;
        int gcol = idx / 320;
        int u = gcol >> 2, g = gcol & 3;
        int r = (k < 256) ? (64 + k) : (k - 256);
        float w = Wc[r * G4 + g * Hn + u];
        __nv_bfloat16 s[3];
        split3(w, s[0], s[1], s[2]);
#pragma unroll
        for (int p = 0; p < 3; p++) g_W[p][gcol][k] = s[p];
    }
    if (idx < G4) {
        int u = idx >> 2, g = idx & 3;
        g_br[idx] = bc[g * Hn + u];
    }
}

__global__ void xsplit_kernel(const float* __restrict__ x) {
    int idx = blockIdx.x * blockDim.x + threadIdx.x;
    int d = idx & 63;
    int tt = (idx >> 6) & 511;
    int b = idx >> 15;
    if (b >= Bn) return;
    float v = x[((size_t)b * Tn + tt) * Dn + d];
    __nv_bfloat16 s[3];
    split3(v, s[0], s[1], s[2]);
#pragma unroll
    for (int p = 0; p < 3; p++) g_xT[p][tt][b][d] = s[p];
}

__global__ void init_kernel() {
    int idx = blockIdx.x * blockDim.x + threadIdx.x;
    if (idx < 3 * Bn * Hn / 2)
        ((unsigned*)g_h[0])[idx] = 0u;
    if (idx < 8) g_bar[idx] = 0;
}

// ---------------- persistent step kernel ----------------
// grid (8, 16): bi = batch slice (128 rows), ci = 16 hidden units (64 gate cols)
__global__ __launch_bounds__(256)
void step_kernel() {
    extern __shared__ char dsm[];
    const uint32_t sbase = smem_u32(dsm);

    const int tid  = threadIdx.x;
    const int lane = tid & 31;
    const int warp = tid >> 5;
    const int wm = warp & 3;
    const int wn = warp >> 2;
    const int bi = blockIdx.x;
    const int ci = blockIdx.y;
    const int row0 = bi * 128;

    // resident B (weights, K=320): 3 planes x 64 cols x 640B, XOR-swizzled
#pragma unroll
    for (int i = 0; i < 30; i++) {
        int flat = i * 256 + tid;                 // < 7680
        int q = flat % 40;
        int n = (flat / 40) & 63;
        int p = flat / 2560;
        uint32_t off = (uint32_t)(q * 16) ^ (uint32_t)((n & 7) << 4);
        cp16(sbase + B_OFF + (uint32_t)(p * 64 + n) * BPITCH + off,
             (const char*)&g_W[p][ci * 64 + n][q * 8]);
    }
    cp_commit();

    float cold[8], nold[8];
#pragma unroll
    for (int q = 0; q < 8; q++) { cold[q] = 0.0f; nold[q] = 1.0f; }

    const int mrow = lane & 15;
    const int kAo  = (lane >> 4) << 3;
    const int nBo  = ((lane >> 4) << 3) + (lane & 7);
    const int kBo  = ((lane >> 3) & 1) << 3;
    const bool odd = lane & 1;
    const int jh = (lane >> 1) & 1;

    float cm[2][4][4], cl[2][4][4], cx[2][4][4];

    // per-(mi,ni) chunk compute: 4 k16 steps, 6-product bf16x6
    auto do_chunk = [&](uint32_t abase, uint32_t bko) {
#pragma unroll
        for (int ks = 0; ks < 4; ks++) {
            uint32_t a[3][2][4], b[3][2][4];
#pragma unroll
            for (int p = 0; p < 3; p++) {
#pragma unroll
                for (int mi = 0; mi < 2; mi++) {
                    int arow = wm * 32 + mi * 16 + mrow;
                    uint32_t off = (uint32_t)((ks * 16 + kAo) * 2) ^ (uint32_t)((arow & 7) << 4);
                    LDSM4(a[p][mi], abase + (uint32_t)(p * 128 + arow) * 128 + off);
                }
#pragma unroll
                for (int pr = 0; pr < 2; pr++) {
                    int brow = wn * 32 + pr * 16 + nBo;
                    uint32_t off = (bko + (uint32_t)((ks * 16 + kBo) * 2)) ^ (uint32_t)((brow & 7) << 4);
                    LDSM4(b[p][pr], sbase + B_OFF + (uint32_t)(p * 64 + brow) * BPITCH + off);
                }
            }
#pragma unroll
            for (int mi = 0; mi < 2; mi++)
#pragma unroll
                for (int ni = 0; ni < 4; ni++) {
                    const int pr = ni >> 1, o = (ni & 1) * 2;
                    mma_bf16(cm[mi][ni], a[0][mi], b[0][pr][o], b[0][pr][o+1]); // hi*hi
                    mma_bf16(cl[mi][ni], a[0][mi], b[1][pr][o], b[1][pr][o+1]); // hi*mid
                    mma_bf16(cl[mi][ni], a[1][mi], b[0][pr][o], b[0][pr][o+1]); // mid*hi
                    mma_bf16(cl[mi][ni], a[0][mi], b[2][pr][o], b[2][pr][o+1]); // hi*lo
                    mma_bf16(cl[mi][ni], a[1][mi], b[1][pr][o], b[1][pr][o+1]); // mid*mid
                    mma_bf16(cl[mi][ni], a[2][mi], b[0][pr][o], b[0][pr][o+1]); // lo*hi
                }
        }
    };

    for (int t = 0; t < Tn; t++) {
        const int hbuf = t & 1;

        // ---- x chunk (k 256..319) into buffer 0: issue + compute BEFORE barrier ----
#pragma unroll
        for (int i = 0; i < 12; i++) {
            int flat = i * 256 + tid;             // < 3072
            int q = flat & 7;
            int m = (flat >> 3) & 127;
            int p = flat >> 10;
            uint32_t off = (uint32_t)(q * 16) ^ (uint32_t)((m & 7) << 4);
            cp16(sbase + (uint32_t)(p * 128 + m) * 128 + off,
                 (const char*)&g_xT[p][t][row0 + m][q * 8]);
        }
        cp_commit();

#pragma unroll
        for (int mi = 0; mi < 2; mi++)
#pragma unroll
            for (int ni = 0; ni < 4; ni++)
#pragma unroll
                for (int q = 0; q < 4; q++) { cm[mi][ni][q] = 0.0f; cl[mi][ni][q] = 0.0f; }

        asm volatile("cp.async.wait_group 0;" ::: "memory");
        __syncthreads();
        do_chunk(sbase, (uint32_t)(256 * 2));     // x part -> cm/cl

        // collapse x part + bias into cx, reset cm/cl
#pragma unroll
        for (int mi = 0; mi < 2; mi++)
#pragma unroll
            for (int ni = 0; ni < 4; ni++) {
                int col = ci * 64 + wn * 32 + ni * 8 + (lane & 3) * 2;
                float b0 = g_br[col], b1 = g_br[col + 1];
                cx[mi][ni][0] = cm[mi][ni][0] + cl[mi][ni][0] + b0;
                cx[mi][ni][1] = cm[mi][ni][1] + cl[mi][ni][1] + b1;
                cx[mi][ni][2] = cm[mi][ni][2] + cl[mi][ni][2] + b0;
                cx[mi][ni][3] = cm[mi][ni][3] + cl[mi][ni][3] + b1;
#pragma unroll
                for (int q = 0; q < 4; q++) { cm[mi][ni][q] = 0.0f; cl[mi][ni][q] = 0.0f; }
            }

        // ---- barrier: wait for h(t) from all 16 CTAs of this bi group ----
        if (t > 0 && tid == 0) {
            const int target = 16 * t;
            while (((volatile int*)g_bar)[bi] < target) { }
            __threadfence();
        }
        __syncthreads();   // also guards buffer-0 LDSM reads before h1 refill

        // ---- h phase: 4 chunks k=64, double-buffered (h0->b1, h1->b0, h2->b1, h3->b0)
        auto issue_h = [&](int ch) {
            const uint32_t abase = sbase + (uint32_t)(((ch & 1) ^ 1)) * ABUF;
#pragma unroll
            for (int i = 0; i < 12; i++) {
                int flat = i * 256 + tid;
                int q = flat & 7;
                int m = (flat >> 3) & 127;
                int p = flat >> 10;
                uint32_t off = (uint32_t)(q * 16) ^ (uint32_t)((m & 7) << 4);
                cp16(abase + (uint32_t)(p * 128 + m) * 128 + off,
                     (const char*)&g_h[hbuf][p][row0 + m][ch * 64 + q * 8]);
            }
            cp_commit();
        };

        issue_h(0);
        issue_h(1);

#pragma unroll 1
        for (int ch = 0; ch < 4; ch++) {
            if (ch == 3) asm volatile("cp.async.wait_group 0;" ::: "memory");
            else         asm volatile("cp.async.wait_group 1;" ::: "memory");
            __syncthreads();

            const uint32_t abase = sbase + (uint32_t)(((ch & 1) ^ 1)) * ABUF;
            do_chunk(abase, (uint32_t)(ch * 128));

            __syncthreads();                       // reads done
            if (ch + 2 < 4) issue_h(ch + 2);
        }

        // ---- epilogue ----
        __nv_bfloat16* Hs = (__nv_bfloat16*)dsm;   // [3][128][16], aliases buffer 0
        const bool last = (t == Tn - 1);

#pragma unroll
        for (int mi = 0; mi < 2; mi++)
#pragma unroll
            for (int ni = 0; ni < 4; ni++) {
                float q0 = (cm[mi][ni][0] + cl[mi][ni][0]) + cx[mi][ni][0];
                float q1 = (cm[mi][ni][1] + cl[mi][ni][1]) + cx[mi][ni][1];
                float q2 = (cm[mi][ni][2] + cl[mi][ni][2]) + cx[mi][ni][2];
                float q3 = (cm[mi][ni][3] + cl[mi][ni][3]) + cx[mi][ni][3];
                float s0 = __shfl_xor_sync(0xFFFFFFFFu, q0, 1);
                float s1 = __shfl_xor_sync(0xFFFFFFFFu, q1, 1);
                float s2 = __shfl_xor_sync(0xFFFFFFFFu, q2, 1);
                float s3 = __shfl_xor_sync(0xFFFFFFFFu, q3, 1);

                float gi = odd ? s2 : q0;
                float gf = odd ? s3 : q1;
                float go = odd ? q2 : s0;
                float gz = odd ? q3 : s1;

                const int row = wm * 32 + mi * 16 + (lane >> 2) + (odd ? 8 : 0);
                const int ul  = wn * 8 + ni * 2 + jh;
                const int qi  = mi * 4 + ni;

                gi = fminf(fmaxf(gi, -5.0f), 5.0f);
                gf = fminf(fmaxf(gf, -5.0f), 5.0f);
                float iv = __expf(gi);
                float fv = __expf(gf);

                float cv = fv * cold[qi] + iv * (1.0f - 2.0f / (__expf(2.0f * gz) + 1.0f));
                cv = fminf(fmaxf(cv, -1e6f), 1e6f);
                float nv = fv * nold[qi] + iv;
                nv = fminf(fmaxf(nv, 1e-6f), 1e6f);
                cold[qi] = cv;
                nold[qi] = nv;

                float ov = 1.0f / (1.0f + __expf(-go));
                float hv = ov * (cv / nv);
                if (!isfinite(hv)) hv = 0.0f;

                __nv_bfloat16 h1, h2, h3;
                split3(hv, h1, h2, h3);
                Hs[(0 * 128 + row) * 16 + ul] = h1;
                Hs[(1 * 128 + row) * 16 + ul] = h2;
                Hs[(2 * 128 + row) * 16 + ul] = h3;
                if (last) g_hfull[(row0 + row) * Hn + ci * 16 + ul] = hv;
            }
        __syncthreads();

        if (!last) {
            const int nbuf = hbuf ^ 1;
#pragma unroll
            for (int i = 0; i < 3; i++) {
                int flat = i * 256 + tid;
                int q = flat & 1;
                int m = (flat >> 1) & 127;
                int p = flat >> 8;
                uint4 v = *(const uint4*)&Hs[(p * 128 + m) * 16 + q * 8];
                *(uint4*)&g_h[nbuf][p][row0 + m][ci * 16 + q * 8] = v;
            }
            __threadfence();
            __syncthreads();                       // Hs reads done; h visible
            if (tid == 0) atomicAdd(&g_bar[bi], 1);
        }
    }
}

// ---------------- heads ----------------
__global__ void heads1_kernel(const float* __restrict__ Wa1, const float* __restrict__ ba1,
                              const float* __restrict__ Wv1, const float* __restrict__ bv1) {
    int idx = blockIdx.x * blockDim.x + threadIdx.x;
    if (idx >= Bn * 128) return;
    int b = idx >> 7;
    int j = idx & 127;
    const float* hrow = g_hfull + b * Hn;
    if (j < MIDn) {
        float s = ba1[j];
#pragma unroll 8
        for (int k = 0; k < Hn; k++) s = fmaf(hrow[k], Wa1[k * MIDn + j], s);
        g_a1[b * MIDn + j] = fmaxf(s, 0.0f);
    } else {
        int jj = j - MIDn;
        float s = bv1[jj];
#pragma unroll 8
        for (int k = 0; k < Hn; k++) s = fmaf(hrow[k], Wv1[k * MIDn + jj], s);
        g_v1[b * MIDn + jj] = fmaxf(s, 0.0f);
    }
}

__global__ void heads2_kernel(const float* __restrict__ Wa2, const float* __restrict__ ba2,
                              const float* __restrict__ Wv2, const float* __restrict__ bv2,
                              float* __restrict__ out) {
    int b = blockIdx.x * blockDim.x + threadIdx.x;
    if (b >= Bn) return;
    float l0 = ba2[0], l1 = ba2[1], l2 = ba2[2];
#pragma unroll 8
    for (int m = 0; m < MIDn; m++) {
        float a = g_a1[b * MIDn + m];
        l0 = fmaf(a, Wa2[m * An + 0], l0);
        l1 = fmaf(a, Wa2[m * An + 1], l1);
        l2 = fmaf(a, Wa2[m * An + 2], l2);
    }
    float mx = fmaxf(l0, fmaxf(l1, l2));
    float e0 = expf(l0 - mx), e1 = expf(l1 - mx), e2 = expf(l2 - mx);
    float s = e0 + e1 + e2;
    out[b * An + 0] = e0 / s;
    out[b * An + 1] = e1 / s;
    out[b * An + 2] = e2 / s;

    float v = bv2[0];
#pragma unroll 8
    for (int m = 0; m < MIDn; m++) v = fmaf(g_v1[b * MIDn + m], Wv2[m], v);
    out[Bn * An + b] = v;
}

// ---------------- launch ----------------
extern "C" void kernel_launch(void* const* d_in, const int* in_sizes, int n_in,
                              void* d_out, int out_size) {
    const float* x   = (const float*)d_in[0];
    const float* Wc  = (const float*)d_in[1];
    const float* bc  = (const float*)d_in[2];
    const float* Wa1 = (const float*)d_in[3];
    const float* ba1 = (const float*)d_in[4];
    const float* Wa2 = (const float*)d_in[5];
    const float* ba2 = (const float*)d_in[6];
    const float* Wv1 = (const float*)d_in[7];
    const float* bv1 = (const float*)d_in[8];
    const float* Wv2 = (const float*)d_in[9];
    const float* bv2 = (const float*)d_in[10];
    float* out = (float*)d_out;

    cudaFuncSetAttribute(step_kernel, cudaFuncAttributeMaxDynamicSharedMemorySize, SMEM_TOT);

    wsplit_kernel<<<(G4 * 320 + 255) / 256, 256>>>(Wc, bc);
    xsplit_kernel<<<(Bn * Tn * Dn + 255) / 256, 256>>>(x);
    init_kernel<<<(3 * Bn * Hn / 2 + 255) / 256, 256>>>();

    step_kernel<<<dim3(8, 16), 256, SMEM_TOT>>>();

    heads1_kernel<<<(Bn * 128 + 255) / 256, 256>>>(Wa1, ba1, Wv1, bv1);
    heads2_kernel<<<(Bn + 255) / 256, 256>>>(Wa2, ba2, Wv2, bv2, out);
}